// round 1
// baseline (speedup 1.0000x reference)
#include <cuda_runtime.h>
#include <cstdint>

#define NB   4
#define NT   4096
#define ND   2048
#define NBOT 256

static constexpr int BM = 128, BN = 128, BK = 16, NTHREADS = 256;
static constexpr int LDAS  = 20;   // smem A:  [m][k], padded stride (conflict-free frag reads)
static constexpr int LDBNK = 20;   // smem B:  [n][k] layout (for W / k operands)
static constexpr int LDBKN = 136;  // smem B:  [k][n] layout (for X operand), (8k+n)%32 bijective

// Scratch (allocation-free rule: __device__ globals)
__device__ float g_q[(size_t)NB * NT * NBOT];
__device__ float g_k[(size_t)NB * NT * NBOT];
__device__ float g_S[(size_t)NB * NT * NT];   // scores, then combined matrix (in place)

__device__ __forceinline__ float to_tf32(float x) {
    uint32_t u;
    asm("cvt.rna.tf32.f32 %0, %1;\n" : "=r"(u) : "f"(x));
    return __uint_as_float(u);
}
__device__ __forceinline__ float4 to_tf32_4(float4 v) {
    v.x = to_tf32(v.x); v.y = to_tf32(v.y);
    v.z = to_tf32(v.z); v.w = to_tf32(v.w);
    return v;
}
__device__ __forceinline__ void mma8(float* c, const uint32_t* a, const uint32_t* b) {
    asm volatile(
        "mma.sync.aligned.m16n8k8.row.col.f32.tf32.tf32.f32 "
        "{%0,%1,%2,%3}, {%4,%5,%6,%7}, {%8,%9}, {%0,%1,%2,%3};\n"
        : "+f"(c[0]), "+f"(c[1]), "+f"(c[2]), "+f"(c[3])
        : "r"(a[0]), "r"(a[1]), "r"(a[2]), "r"(a[3]), "r"(b[0]), "r"(b[1]));
}

// EPI: 0 = plain store, 1 = +bias[col], 2 = scale + causal(diag=-4) mask -> -65000
// BNK: true  -> global B is [n][k] (row n contiguous in k)   : W, k-proj
//      false -> global B is [k][n] (row k contiguous in n)   : X
template <int EPI, bool BNK>
__global__ void __launch_bounds__(NTHREADS, 2)
gemm_tf32(const float* __restrict__ A, int lda, long long sA,
          const float* __restrict__ Bg, int ldb, long long sB,
          float* __restrict__ C, int ldc, long long sC,
          int K, const float* __restrict__ bias, float scale)
{
    const int m0 = blockIdx.y * BM;
    const int n0 = blockIdx.x * BN;
    A  += (long long)blockIdx.z * sA;
    Bg += (long long)blockIdx.z * sB;
    C  += (long long)blockIdx.z * sC;
    const int tid = threadIdx.x;

    if (EPI == 2 && n0 > m0) {
        // whole tile strictly above diagonal band -> fully masked
        const float4 f = make_float4(-65000.f, -65000.f, -65000.f, -65000.f);
#pragma unroll
        for (int i = 0; i < (BM * BN / 4) / NTHREADS; ++i) {
            int e = i * NTHREADS + tid;
            int r = e >> 5, c = e & 31;   // BN/4 = 32 float4 per row
            *reinterpret_cast<float4*>(&C[(long long)(m0 + r) * ldc + n0 + c * 4]) = f;
        }
        return;
    }

    __shared__ float As[BM * LDAS];   // 2560 floats
    __shared__ float Bs[BM * LDBNK];  // 2560 floats (>= 16*136 = 2176)

    const int wid = tid >> 5, lane = tid & 31;
    const int wm = (wid & 1) * 64;    // warp tile: 64(m) x 32(n)
    const int wn = (wid >> 1) * 32;
    const int g = lane >> 2, tg = lane & 3;

    float acc[4][4][4];
#pragma unroll
    for (int mi = 0; mi < 4; ++mi)
#pragma unroll
        for (int ni = 0; ni < 4; ++ni)
#pragma unroll
            for (int j = 0; j < 4; ++j) acc[mi][ni][j] = 0.f;

    // staging indices
    const int rA = tid >> 2, cA = (tid & 3) * 4;   // A and B(NK): 64 rows / iter
    const int rB = tid >> 5, cB = (tid & 31) * 4;  // B(KN): 8 k-rows / iter

    float4 ra0, ra1, rb0, rb1;
    const int KT = K / BK;

    // prologue: load tile 0
    ra0 = *reinterpret_cast<const float4*>(&A[(long long)(m0 + rA) * lda + cA]);
    ra1 = *reinterpret_cast<const float4*>(&A[(long long)(m0 + rA + 64) * lda + cA]);
    if (BNK) {
        rb0 = *reinterpret_cast<const float4*>(&Bg[(long long)(n0 + rA) * ldb + cA]);
        rb1 = *reinterpret_cast<const float4*>(&Bg[(long long)(n0 + rA + 64) * ldb + cA]);
    } else {
        rb0 = *reinterpret_cast<const float4*>(&Bg[(long long)rB * ldb + n0 + cB]);
        rb1 = *reinterpret_cast<const float4*>(&Bg[(long long)(rB + 8) * ldb + n0 + cB]);
    }

    for (int kt = 0; kt < KT; ++kt) {
        __syncthreads();
        *reinterpret_cast<float4*>(&As[rA * LDAS + cA])        = to_tf32_4(ra0);
        *reinterpret_cast<float4*>(&As[(rA + 64) * LDAS + cA]) = to_tf32_4(ra1);
        if (BNK) {
            *reinterpret_cast<float4*>(&Bs[rA * LDBNK + cA])        = to_tf32_4(rb0);
            *reinterpret_cast<float4*>(&Bs[(rA + 64) * LDBNK + cA]) = to_tf32_4(rb1);
        } else {
            *reinterpret_cast<float4*>(&Bs[rB * LDBKN + cB])       = to_tf32_4(rb0);
            *reinterpret_cast<float4*>(&Bs[(rB + 8) * LDBKN + cB]) = to_tf32_4(rb1);
        }
        __syncthreads();

        if (kt + 1 < KT) {  // prefetch next tile (overlaps with mma below)
            const int ko = (kt + 1) * BK;
            ra0 = *reinterpret_cast<const float4*>(&A[(long long)(m0 + rA) * lda + ko + cA]);
            ra1 = *reinterpret_cast<const float4*>(&A[(long long)(m0 + rA + 64) * lda + ko + cA]);
            if (BNK) {
                rb0 = *reinterpret_cast<const float4*>(&Bg[(long long)(n0 + rA) * ldb + ko + cA]);
                rb1 = *reinterpret_cast<const float4*>(&Bg[(long long)(n0 + rA + 64) * ldb + ko + cA]);
            } else {
                rb0 = *reinterpret_cast<const float4*>(&Bg[(long long)(ko + rB) * ldb + n0 + cB]);
                rb1 = *reinterpret_cast<const float4*>(&Bg[(long long)(ko + rB + 8) * ldb + n0 + cB]);
            }
        }

#pragma unroll
        for (int ks = 0; ks < 2; ++ks) {
            const int kk = ks * 8;
            uint32_t af[4][4], bf[4][2];
#pragma unroll
            for (int mi = 0; mi < 4; ++mi) {
                const int r = wm + mi * 16 + g;
                af[mi][0] = __float_as_uint(As[r * LDAS + kk + tg]);
                af[mi][1] = __float_as_uint(As[(r + 8) * LDAS + kk + tg]);
                af[mi][2] = __float_as_uint(As[r * LDAS + kk + tg + 4]);
                af[mi][3] = __float_as_uint(As[(r + 8) * LDAS + kk + tg + 4]);
            }
#pragma unroll
            for (int ni = 0; ni < 4; ++ni) {
                const int nn = wn + ni * 8 + g;
                if (BNK) {
                    bf[ni][0] = __float_as_uint(Bs[nn * LDBNK + kk + tg]);
                    bf[ni][1] = __float_as_uint(Bs[nn * LDBNK + kk + tg + 4]);
                } else {
                    bf[ni][0] = __float_as_uint(Bs[(kk + tg) * LDBKN + nn]);
                    bf[ni][1] = __float_as_uint(Bs[(kk + tg + 4) * LDBKN + nn]);
                }
            }
#pragma unroll
            for (int mi = 0; mi < 4; ++mi)
#pragma unroll
                for (int ni = 0; ni < 4; ++ni)
                    mma8(acc[mi][ni], af[mi], bf[ni]);
        }
    }

    // epilogue
#pragma unroll
    for (int mi = 0; mi < 4; ++mi) {
#pragma unroll
        for (int ni = 0; ni < 4; ++ni) {
            const int row = m0 + wm + mi * 16 + g;
            const int col = n0 + wn + ni * 8 + 2 * tg;
            float v0 = acc[mi][ni][0], v1 = acc[mi][ni][1];
            float v2 = acc[mi][ni][2], v3 = acc[mi][ni][3];
            if (EPI == 1) {
                const float b0 = __ldg(&bias[col]), b1 = __ldg(&bias[col + 1]);
                v0 += b0; v1 += b1; v2 += b0; v3 += b1;
            }
            if (EPI == 2) {
                v0 = (col     + 4 <= row)     ? v0 * scale : -65000.f;
                v1 = (col + 1 + 4 <= row)     ? v1 * scale : -65000.f;
                v2 = (col     + 4 <= row + 8) ? v2 * scale : -65000.f;
                v3 = (col + 1 + 4 <= row + 8) ? v3 * scale : -65000.f;
            }
            *reinterpret_cast<float2*>(&C[(long long)row * ldc + col])       = make_float2(v0, v1);
            *reinterpret_cast<float2*>(&C[(long long)(row + 8) * ldc + col]) = make_float2(v2, v3);
        }
    }
}

// One block per row (b*T + i): row max, sum-exp, then C = 0.7*decay + 0.3*P (in place on S).
__global__ void __launch_bounds__(256)
softmax_combine(const float* __restrict__ decay, float* __restrict__ S)
{
    __shared__ float red[8];
    const long long base = (long long)blockIdx.x * NT;
    const int tid = threadIdx.x;
    const int lane = tid & 31, wid = tid >> 5;

    float v[16];
#pragma unroll
    for (int p = 0; p < 16; ++p) v[p] = S[base + tid + 256 * p];

    float mx = v[0];
#pragma unroll
    for (int p = 1; p < 16; ++p) mx = fmaxf(mx, v[p]);
#pragma unroll
    for (int o = 16; o > 0; o >>= 1) mx = fmaxf(mx, __shfl_xor_sync(0xffffffffu, mx, o));
    if (lane == 0) red[wid] = mx;
    __syncthreads();
    float bm = red[0];
#pragma unroll
    for (int i = 1; i < 8; ++i) bm = fmaxf(bm, red[i]);

    float s = 0.f;
#pragma unroll
    for (int p = 0; p < 16; ++p) { v[p] = __expf(v[p] - bm); s += v[p]; }
#pragma unroll
    for (int o = 16; o > 0; o >>= 1) s += __shfl_xor_sync(0xffffffffu, s, o);
    __syncthreads();   // everyone done reading red[] for max
    if (lane == 0) red[wid] = s;
    __syncthreads();
    float ts = 0.f;
#pragma unroll
    for (int i = 0; i < 8; ++i) ts += red[i];

    const float inv = 0.3f / ts;
#pragma unroll
    for (int p = 0; p < 16; ++p) {
        const long long idx = base + tid + 256 * p;
        S[idx] = fmaf(v[p], inv, 0.7f * decay[idx]);
    }
}

extern "C" void kernel_launch(void* const* d_in, const int* in_sizes, int n_in,
                              void* d_out, int out_size)
{
    (void)in_sizes; (void)n_in; (void)out_size;
    const float* X     = (const float*)d_in[0];  // [B,T,D]
    const float* decay = (const float*)d_in[1];  // [B,T,T]
    const float* Wq    = (const float*)d_in[2];  // [BOT,D]
    const float* bq    = (const float*)d_in[3];
    const float* Wk    = (const float*)d_in[4];
    const float* bk    = (const float*)d_in[5];
    float*       out   = (float*)d_out;          // [B,T,D]

    float *qp, *kp, *Sp;
    cudaGetSymbolAddress((void**)&qp, g_q);
    cudaGetSymbolAddress((void**)&kp, g_k);
    cudaGetSymbolAddress((void**)&Sp, g_S);

    const dim3 blk(NTHREADS);

    // q = X @ Wq^T + bq ; k = X @ Wk^T + bk   (M=B*T, N=BOT, K=D)
    gemm_tf32<1, true><<<dim3(NBOT / BN, (NB * NT) / BM, 1), blk>>>(
        X, ND, 0LL, Wq, ND, 0LL, qp, NBOT, 0LL, ND, bq, 1.f);
    gemm_tf32<1, true><<<dim3(NBOT / BN, (NB * NT) / BM, 1), blk>>>(
        X, ND, 0LL, Wk, ND, 0LL, kp, NBOT, 0LL, ND, bk, 1.f);

    // S = scale * q @ k^T with causal(diag=-4) mask  (per batch, M=N=T, K=BOT)
    gemm_tf32<2, true><<<dim3(NT / BN, NT / BM, NB), blk>>>(
        qp, NBOT, (long long)NT * NBOT,
        kp, NBOT, (long long)NT * NBOT,
        Sp, NT,   (long long)NT * NT,
        NBOT, nullptr, 0.0625f /* BOT^-0.5 */);

    // row softmax + 0.7*decay + 0.3*P   (in place on S)
    softmax_combine<<<NB * NT, 256>>>(decay, Sp);

    // out = C @ X   (per batch, M=T, N=D, K=T)
    gemm_tf32<0, false><<<dim3(ND / BN, NT / BM, NB), blk>>>(
        Sp, NT, (long long)NT * NT,
        X,  ND, (long long)NT * ND,
        out, ND, (long long)NT * ND,
        NT, nullptr, 1.f);
}

// round 4
// speedup vs baseline: 2.3346x; 2.3346x over previous
#include <cuda_runtime.h>
#include <cuda_fp16.h>
#include <cstdint>

#define NB   4
#define NT   4096
#define ND   2048
#define NBOT 256
#define NQK  512        // merged q|k output width

static constexpr int BM = 128, BN = 128, BK = 32, NTH = 128, NSTAGE = 3;
static constexpr int STAGE_B   = BM * 64 + BN * 64;   // A 8KB + B 8KB = 16KB (fp16, 64B/row)
static constexpr int SMEM_BYTES = NSTAGE * STAGE_B;   // 48 KB

// ---- scratch (__device__ globals: allocation-free rule) ----
__device__ __align__(256) float  g_S [(size_t)NB * NT * NT];    // fp32 scores
__device__ __align__(256) __half g_C [(size_t)NB * NT * NT];    // fp16 combined matrix
__device__ __align__(256) __half g_Xh [(size_t)NB * NT * ND];   // X  fp16
__device__ __align__(256) __half g_Xth[(size_t)NB * ND * NT];   // X^T fp16
__device__ __align__(256) __half g_qk[(size_t)NB * NT * NQK];   // [q|k] fp16
__device__ __align__(256) __half g_W [(size_t)NQK * ND];        // [Wq;Wk] fp16
__device__ __align__(256) float  g_bias[NQK];

// ---- helpers ----
__device__ __forceinline__ uint32_t smem_u32(const void* p) {
    uint32_t a;
    asm("{ .reg .u64 t; cvta.to.shared.u64 t, %1; cvt.u32.u64 %0, t; }" : "=r"(a) : "l"(p));
    return a;
}
__device__ __forceinline__ void cp16(uint32_t dst, const __half* src) {
    asm volatile("cp.async.cg.shared.global [%0], [%1], 16;\n"
                 :: "r"(dst), "l"(__cvta_generic_to_global(src)));
}
#define CP_COMMIT()  asm volatile("cp.async.commit_group;\n" ::: "memory")
#define CP_WAIT(n)   asm volatile("cp.async.wait_group %0;\n" :: "n"(n) : "memory")

__device__ __forceinline__ void mma16(float* c, uint32_t a0, uint32_t a1, uint32_t a2,
                                      uint32_t a3, uint32_t b0, uint32_t b1) {
    asm volatile(
        "mma.sync.aligned.m16n8k16.row.col.f32.f16.f16.f32 "
        "{%0,%1,%2,%3}, {%4,%5,%6,%7}, {%8,%9}, {%0,%1,%2,%3};\n"
        : "+f"(c[0]), "+f"(c[1]), "+f"(c[2]), "+f"(c[3])
        : "r"(a0), "r"(a1), "r"(a2), "r"(a3), "r"(b0), "r"(b1));
}

// ============================================================================
// fp16 mma.sync GEMM: D[m][n] = sum_k A[m][k] * B[n][k]  (A,B fp16 row-major K-contig)
// EPI: 0 = fp32 store, 1 = +bias -> fp16 store, 2 = scale + causal(-4) mask -> fp32
// Warp tile 64x64 (4 warps), BK=32, 3-stage cp.async.
// Frag loads use a per-thread k-permutation (thread tg supplies k in {8tg..8tg+7});
// A and B use the same slot->k map, so the mma result is the true sum over k.
// ============================================================================
template <int EPI>
__global__ void __launch_bounds__(NTH, 2)
gemm_h(const __half* __restrict__ A, int lda, long long strA,
       const __half* __restrict__ Bg, int ldb, long long strB,
       void* __restrict__ Cv, int ldc, long long strC,
       int K, const float* __restrict__ bias, float scale)
{
    const int m0 = blockIdx.y * BM;
    const int n0 = blockIdx.x * BN;
    const int bz = blockIdx.z;
    A  += (long long)bz * strA;
    Bg += (long long)bz * strB;
    const int tid = threadIdx.x, wid = tid >> 5, lane = tid & 31;
    const int g = lane >> 2, tg = lane & 3;

    if (EPI == 2 && n0 > m0) {   // tile fully masked (diag=-4, 128-multiples)
        float* C = (float*)Cv + (long long)bz * strC;
        const float4 f = make_float4(-65000.f, -65000.f, -65000.f, -65000.f);
#pragma unroll
        for (int i = 0; i < 32; ++i) {
            int e = i * NTH + tid;
            int r = e >> 5, c4 = e & 31;
            *reinterpret_cast<float4*>(&C[(long long)(m0 + r) * ldc + n0 + c4 * 4]) = f;
        }
        return;
    }

    extern __shared__ char smem[];
    const uint32_t sbase = smem_u32(smem);

    float acc[4][8][4];
#pragma unroll
    for (int mi = 0; mi < 4; ++mi)
#pragma unroll
        for (int ni = 0; ni < 8; ++ni)
#pragma unroll
            for (int j = 0; j < 4; ++j) acc[mi][ni][j] = 0.f;

    auto load_stage = [&](int s, int j) {
        const uint32_t sa = sbase + s * STAGE_B;
        const uint32_t sb = sa + BM * 64;
#pragma unroll
        for (int i = 0; i < 4; ++i) {            // A: 128 rows x 64B
            int id = i * NTH + tid, r = id >> 2, c = id & 3;
            cp16(sa + r * 64 + c * 16, &A[(long long)(m0 + r) * lda + j * 32 + c * 8]);
        }
#pragma unroll
        for (int i = 0; i < 4; ++i) {            // B: 128 rows x 64B
            int id = i * NTH + tid, r = id >> 2, c = id & 3;
            cp16(sb + r * 64 + c * 16, &Bg[(long long)(n0 + r) * ldb + j * 32 + c * 8]);
        }
    };

    const int KT = K / BK;
    load_stage(0, 0); CP_COMMIT();
    load_stage(1, 1); CP_COMMIT();

    const int wm = (wid & 1) * 64, wn = (wid >> 1) * 64;

    for (int kt = 0; kt < KT; ++kt) {
        CP_WAIT(1);
        __syncthreads();
        const int s = kt % 3;
        if (kt + 2 < KT) load_stage((kt + 2) % 3, kt + 2);
        CP_COMMIT();

        const char* sa = smem + s * STAGE_B;
        const char* sb = sa + BM * 64;

        uint4 vb[8];
#pragma unroll
        for (int ni = 0; ni < 8; ++ni)
            vb[ni] = *reinterpret_cast<const uint4*>(sb + (wn + 8 * ni + g) * 64 + tg * 16);
#pragma unroll
        for (int mi = 0; mi < 4; ++mi) {
            const uint4 va0 = *reinterpret_cast<const uint4*>(sa + (wm + 16 * mi + g) * 64 + tg * 16);
            const uint4 va1 = *reinterpret_cast<const uint4*>(sa + (wm + 16 * mi + g + 8) * 64 + tg * 16);
#pragma unroll
            for (int ni = 0; ni < 8; ++ni)   // k-group 0: halves 0..3 of each row chunk
                mma16(acc[mi][ni], va0.x, va1.x, va0.y, va1.y, vb[ni].x, vb[ni].y);
#pragma unroll
            for (int ni = 0; ni < 8; ++ni)   // k-group 1: halves 4..7
                mma16(acc[mi][ni], va0.z, va1.z, va0.w, va1.w, vb[ni].z, vb[ni].w);
        }
    }

    // ---- epilogue: direct fragment stores ----
#pragma unroll
    for (int mi = 0; mi < 4; ++mi) {
#pragma unroll
        for (int ni = 0; ni < 8; ++ni) {
            const int row = m0 + wm + 16 * mi + g;
            const int col = n0 + wn + 8 * ni + 2 * tg;
            float v0 = acc[mi][ni][0], v1 = acc[mi][ni][1];
            float v2 = acc[mi][ni][2], v3 = acc[mi][ni][3];
            if (EPI == 1) {
                __half* C = (__half*)Cv + (long long)bz * strC;
                const float2 bv = *reinterpret_cast<const float2*>(&bias[col]);
                *reinterpret_cast<__half2*>(&C[(long long)row * ldc + col]) =
                    __floats2half2_rn(v0 + bv.x, v1 + bv.y);
                *reinterpret_cast<__half2*>(&C[(long long)(row + 8) * ldc + col]) =
                    __floats2half2_rn(v2 + bv.x, v3 + bv.y);
            } else {
                float* C = (float*)Cv + (long long)bz * strC;
                if (EPI == 2) {
                    v0 = (col + 4     <= row)     ? v0 * scale : -65000.f;
                    v1 = (col + 1 + 4 <= row)     ? v1 * scale : -65000.f;
                    v2 = (col + 4     <= row + 8) ? v2 * scale : -65000.f;
                    v3 = (col + 1 + 4 <= row + 8) ? v3 * scale : -65000.f;
                }
                *reinterpret_cast<float2*>(&C[(long long)row * ldc + col])       = make_float2(v0, v1);
                *reinterpret_cast<float2*>(&C[(long long)(row + 8) * ldc + col]) = make_float2(v2, v3);
            }
        }
    }
}

// ---- prep: W -> fp16 merged [Wq;Wk], bias merged fp32 ----
__global__ void prep_w(const float* __restrict__ Wq, const float* __restrict__ Wk,
                       const float* __restrict__ bq, const float* __restrict__ bk,
                       __half* __restrict__ W, float* __restrict__ bias) {
    const int row = blockIdx.x;
    const float* src = (row < NBOT) ? &Wq[(size_t)row * ND] : &Wk[(size_t)(row - NBOT) * ND];
    for (int c = threadIdx.x; c < ND; c += blockDim.x)
        W[(size_t)row * ND + c] = __float2half_rn(src[c]);
    if (threadIdx.x == 0)
        bias[row] = (row < NBOT) ? bq[row] : bk[row - NBOT];
}

// ---- prep: X fp32 -> fp16 copy + fp16 transpose ----
__global__ void transpose_half(const float* __restrict__ X,
                               __half* __restrict__ Xh, __half* __restrict__ Xt) {
    __shared__ float tile[32][33];
    const int b = blockIdx.z;
    const int d0 = blockIdx.x * 32, t0 = blockIdx.y * 32;
    const float* Xb = X  + (long long)b * NT * ND;
    __half* Xhb     = Xh + (long long)b * NT * ND;
    __half* Xtb     = Xt + (long long)b * ND * NT;
    const int tx = threadIdx.x, ty = threadIdx.y;
#pragma unroll
    for (int i = 0; i < 4; ++i) {
        const int t = t0 + ty + i * 8;
        const float v = Xb[(long long)t * ND + d0 + tx];
        Xhb[(long long)t * ND + d0 + tx] = __float2half_rn(v);
        tile[ty + i * 8][tx] = v;
    }
    __syncthreads();
#pragma unroll
    for (int i = 0; i < 4; ++i) {
        const int d = d0 + ty + i * 8;
        Xtb[(long long)d * NT + t0 + tx] = __float2half_rn(tile[tx][ty + i * 8]);
    }
}

// ---- softmax + combine: fp32 scores in, fp16 combined out ----
__global__ void __launch_bounds__(256)
softmax_combine(const float* __restrict__ decay, const float* __restrict__ S,
                __half* __restrict__ C)
{
    __shared__ float red[8];
    const long long base = (long long)blockIdx.x * NT;
    const int tid = threadIdx.x;
    const int lane = tid & 31, wid = tid >> 5;

    float v[16];
#pragma unroll
    for (int p = 0; p < 16; ++p) v[p] = S[base + tid + 256 * p];

    float mx = v[0];
#pragma unroll
    for (int p = 1; p < 16; ++p) mx = fmaxf(mx, v[p]);
#pragma unroll
    for (int o = 16; o > 0; o >>= 1) mx = fmaxf(mx, __shfl_xor_sync(0xffffffffu, mx, o));
    if (lane == 0) red[wid] = mx;
    __syncthreads();
    float bm = red[0];
#pragma unroll
    for (int i = 1; i < 8; ++i) bm = fmaxf(bm, red[i]);

    float s = 0.f;
#pragma unroll
    for (int p = 0; p < 16; ++p) { v[p] = __expf(v[p] - bm); s += v[p]; }
#pragma unroll
    for (int o = 16; o > 0; o >>= 1) s += __shfl_xor_sync(0xffffffffu, s, o);
    __syncthreads();
    if (lane == 0) red[wid] = s;
    __syncthreads();
    float ts = 0.f;
#pragma unroll
    for (int i = 0; i < 8; ++i) ts += red[i];

    const float inv = 0.3f / ts;
#pragma unroll
    for (int p = 0; p < 16; ++p) {
        const long long idx = base + tid + 256 * p;
        C[idx] = __float2half_rn(fmaf(v[p], inv, 0.7f * decay[idx]));
    }
}

extern "C" void kernel_launch(void* const* d_in, const int* in_sizes, int n_in,
                              void* d_out, int out_size)
{
    (void)in_sizes; (void)n_in; (void)out_size;
    const float* X     = (const float*)d_in[0];
    const float* decay = (const float*)d_in[1];
    const float* Wq    = (const float*)d_in[2];
    const float* bq    = (const float*)d_in[3];
    const float* Wk    = (const float*)d_in[4];
    const float* bk    = (const float*)d_in[5];
    float*       out   = (float*)d_out;

    float  *Sp, *biasp;
    __half *Cp, *Xhp, *Xtp, *qkp, *Wp;
    cudaGetSymbolAddress((void**)&Sp,   g_S);
    cudaGetSymbolAddress((void**)&Cp,   g_C);
    cudaGetSymbolAddress((void**)&Xhp,  g_Xh);
    cudaGetSymbolAddress((void**)&Xtp,  g_Xth);
    cudaGetSymbolAddress((void**)&qkp,  g_qk);
    cudaGetSymbolAddress((void**)&Wp,   g_W);
    cudaGetSymbolAddress((void**)&biasp, g_bias);

    cudaFuncSetAttribute(gemm_h<0>, cudaFuncAttributeMaxDynamicSharedMemorySize, SMEM_BYTES);
    cudaFuncSetAttribute(gemm_h<1>, cudaFuncAttributeMaxDynamicSharedMemorySize, SMEM_BYTES);
    cudaFuncSetAttribute(gemm_h<2>, cudaFuncAttributeMaxDynamicSharedMemorySize, SMEM_BYTES);

    // prep
    prep_w<<<NQK, 256>>>(Wq, Wk, bq, bk, Wp, biasp);
    transpose_half<<<dim3(ND / 32, NT / 32, NB), dim3(32, 8)>>>(X, Xhp, Xtp);

    // qk = X @ [Wq;Wk]^T + bias   (M = B*T = 16384, N = 512, K = 2048) -> fp16
    gemm_h<1><<<dim3(NQK / BN, (NB * NT) / BM, 1), NTH, SMEM_BYTES>>>(
        Xhp, ND, 0LL, Wp, ND, 0LL, qkp, NQK, 0LL, ND, biasp, 1.f);

    // S = scale * q @ k^T + causal(-4) mask   (per batch, M = N = T, K = 256) -> fp32
    gemm_h<2><<<dim3(NT / BN, NT / BM, NB), NTH, SMEM_BYTES>>>(
        qkp,        NQK, (long long)NT * NQK,
        qkp + NBOT, NQK, (long long)NT * NQK,
        Sp,         NT,  (long long)NT * NT,
        NBOT, nullptr, 0.0625f);

    // combined = 0.7*decay + 0.3*softmax(S)  -> fp16
    softmax_combine<<<NB * NT, 256>>>(decay, Sp, Cp);

    // out = combined @ X = combined @ Xt^T  (per batch, M = T, N = D, K = T) -> fp32
    gemm_h<0><<<dim3(ND / BN, NT / BM, NB), NTH, SMEM_BYTES>>>(
        Cp,  NT, (long long)NT * NT,
        Xtp, NT, (long long)ND * NT,
        out, ND, (long long)NT * ND,
        NT, nullptr, 1.f);
}

// round 5
// speedup vs baseline: 2.3977x; 1.0271x over previous
#include <cuda_runtime.h>
#include <cuda_fp16.h>
#include <cstdint>

#define NB   4
#define NT   4096
#define ND   2048
#define NBOT 256
#define NQK  512        // merged q|k output width

static constexpr int BM = 128, BN = 128, BK = 32, NTH = 256, NSTAGE = 4;
static constexpr int STAGE_B   = BM * 64 + BN * 64;   // A 8KB + B 8KB (fp16, 64B/row)
static constexpr int SMEM_BYTES = NSTAGE * STAGE_B;   // 64 KB

// ---- scratch (__device__ globals: allocation-free rule) ----
__device__ __align__(256) float  g_S [(size_t)NB * NT * NT];    // fp32 scores (lower tri only)
__device__ __align__(256) __half g_C [(size_t)NB * NT * NT];    // fp16 combined matrix
__device__ __align__(256) __half g_Xh [(size_t)NB * NT * ND];   // X  fp16
__device__ __align__(256) __half g_Xth[(size_t)NB * ND * NT];   // X^T fp16
__device__ __align__(256) __half g_qk[(size_t)NB * NT * NQK];   // [q|k] fp16
__device__ __align__(256) __half g_W [(size_t)NQK * ND];        // [Wq;Wk] fp16
__device__ __align__(256) float  g_bias[NQK];

// ---- helpers ----
__device__ __forceinline__ uint32_t smem_u32(const void* p) {
    uint32_t a;
    asm("{ .reg .u64 t; cvta.to.shared.u64 t, %1; cvt.u32.u64 %0, t; }" : "=r"(a) : "l"(p));
    return a;
}
__device__ __forceinline__ void cp16(uint32_t dst, const __half* src) {
    asm volatile("cp.async.cg.shared.global [%0], [%1], 16;\n"
                 :: "r"(dst), "l"(__cvta_generic_to_global(src)));
}
#define CP_COMMIT()  asm volatile("cp.async.commit_group;\n" ::: "memory")
#define CP_WAIT(n)   asm volatile("cp.async.wait_group %0;\n" :: "n"(n) : "memory")

__device__ __forceinline__ void mma16(float* c, uint32_t a0, uint32_t a1, uint32_t a2,
                                      uint32_t a3, uint32_t b0, uint32_t b1) {
    asm volatile(
        "mma.sync.aligned.m16n8k16.row.col.f32.f16.f16.f32 "
        "{%0,%1,%2,%3}, {%4,%5,%6,%7}, {%8,%9}, {%0,%1,%2,%3};\n"
        : "+f"(c[0]), "+f"(c[1]), "+f"(c[2]), "+f"(c[3])
        : "r"(a0), "r"(a1), "r"(a2), "r"(a3), "r"(b0), "r"(b1));
}

// ============================================================================
// fp16 mma.sync GEMM: D[m][n] = sum_k A[m][k] * B[n][k]  (A,B fp16 row-major K-contig)
// EPI: 0 = fp32 store, 1 = +bias -> fp16 store, 2 = scale + causal(-4) mask -> fp32
//      (EPI 2: upper-triangular tiles are skipped entirely; softmax never reads them)
// 8 warps (2m x 4n), warp tile 64x32, BK=32, 4-stage cp.async, 2 CTAs/SM.
// Frag loads use a per-thread k-slot permutation (thread tg supplies k in {8tg..8tg+7});
// A and B use the same slot->k map, so the mma result is the true sum over k.
// ============================================================================
template <int EPI>
__global__ void __launch_bounds__(NTH, 2)
gemm_h(const __half* __restrict__ A, int lda, long long strA,
       const __half* __restrict__ Bg, int ldb, long long strB,
       void* __restrict__ Cv, int ldc, long long strC,
       int K, const float* __restrict__ bias, float scale)
{
    const int m0 = blockIdx.y * BM;
    const int n0 = blockIdx.x * BN;
    const int bz = blockIdx.z;
    if (EPI == 2 && n0 > m0) return;   // fully masked tile: never written, never read

    A  += (long long)bz * strA;
    Bg += (long long)bz * strB;
    const int tid = threadIdx.x, wid = tid >> 5, lane = tid & 31;
    const int g = lane >> 2, tg = lane & 3;

    extern __shared__ char smem[];
    const uint32_t sbase = smem_u32(smem);

    float acc[4][4][4];
#pragma unroll
    for (int mi = 0; mi < 4; ++mi)
#pragma unroll
        for (int ni = 0; ni < 4; ++ni)
#pragma unroll
            for (int j = 0; j < 4; ++j) acc[mi][ni][j] = 0.f;

    auto load_stage = [&](int s, int j) {
        const uint32_t sa = sbase + s * STAGE_B;
        const uint32_t sb = sa + BM * 64;
#pragma unroll
        for (int i = 0; i < 2; ++i) {            // A: 128 rows x 64B
            int id = i * NTH + tid, r = id >> 2, c = id & 3;
            cp16(sa + r * 64 + c * 16, &A[(long long)(m0 + r) * lda + j * 32 + c * 8]);
        }
#pragma unroll
        for (int i = 0; i < 2; ++i) {            // B: 128 rows x 64B
            int id = i * NTH + tid, r = id >> 2, c = id & 3;
            cp16(sb + r * 64 + c * 16, &Bg[(long long)(n0 + r) * ldb + j * 32 + c * 8]);
        }
    };

    const int KT = K / BK;
#pragma unroll
    for (int s = 0; s < NSTAGE - 1; ++s) { load_stage(s, s); CP_COMMIT(); }

    const int wm = (wid & 1) * 64, wn = (wid >> 1) * 32;

    for (int kt = 0; kt < KT; ++kt) {
        CP_WAIT(NSTAGE - 2);
        __syncthreads();
        const int s = kt & (NSTAGE - 1);
        if (kt + NSTAGE - 1 < KT) load_stage((kt + NSTAGE - 1) & (NSTAGE - 1), kt + NSTAGE - 1);
        CP_COMMIT();

        const char* sa = smem + s * STAGE_B;
        const char* sb = sa + BM * 64;

        uint4 vb[4];
#pragma unroll
        for (int ni = 0; ni < 4; ++ni)
            vb[ni] = *reinterpret_cast<const uint4*>(sb + (wn + 8 * ni + g) * 64 + tg * 16);
#pragma unroll
        for (int mi = 0; mi < 4; ++mi) {
            const uint4 va0 = *reinterpret_cast<const uint4*>(sa + (wm + 16 * mi + g) * 64 + tg * 16);
            const uint4 va1 = *reinterpret_cast<const uint4*>(sa + (wm + 16 * mi + g + 8) * 64 + tg * 16);
#pragma unroll
            for (int ni = 0; ni < 4; ++ni)   // k-slots 0..3
                mma16(acc[mi][ni], va0.x, va1.x, va0.y, va1.y, vb[ni].x, vb[ni].y);
#pragma unroll
            for (int ni = 0; ni < 4; ++ni)   // k-slots 4..7
                mma16(acc[mi][ni], va0.z, va1.z, va0.w, va1.w, vb[ni].z, vb[ni].w);
        }
    }

    // ---- epilogue: direct fragment stores ----
#pragma unroll
    for (int mi = 0; mi < 4; ++mi) {
#pragma unroll
        for (int ni = 0; ni < 4; ++ni) {
            const int row = m0 + wm + 16 * mi + g;
            const int col = n0 + wn + 8 * ni + 2 * tg;
            float v0 = acc[mi][ni][0], v1 = acc[mi][ni][1];
            float v2 = acc[mi][ni][2], v3 = acc[mi][ni][3];
            if (EPI == 1) {
                __half* C = (__half*)Cv + (long long)bz * strC;
                const float2 bv = *reinterpret_cast<const float2*>(&bias[col]);
                *reinterpret_cast<__half2*>(&C[(long long)row * ldc + col]) =
                    __floats2half2_rn(v0 + bv.x, v1 + bv.y);
                *reinterpret_cast<__half2*>(&C[(long long)(row + 8) * ldc + col]) =
                    __floats2half2_rn(v2 + bv.x, v3 + bv.y);
            } else {
                float* C = (float*)Cv + (long long)bz * strC;
                if (EPI == 2) {
                    v0 = (col + 4     <= row)     ? v0 * scale : -65000.f;
                    v1 = (col + 1 + 4 <= row)     ? v1 * scale : -65000.f;
                    v2 = (col + 4     <= row + 8) ? v2 * scale : -65000.f;
                    v3 = (col + 1 + 4 <= row + 8) ? v3 * scale : -65000.f;
                }
                *reinterpret_cast<float2*>(&C[(long long)row * ldc + col])       = make_float2(v0, v1);
                *reinterpret_cast<float2*>(&C[(long long)(row + 8) * ldc + col]) = make_float2(v2, v3);
            }
        }
    }
}

// ---- prep: W -> fp16 merged [Wq;Wk], bias merged fp32 ----
__global__ void prep_w(const float* __restrict__ Wq, const float* __restrict__ Wk,
                       const float* __restrict__ bq, const float* __restrict__ bk,
                       __half* __restrict__ W, float* __restrict__ bias) {
    const int row = blockIdx.x;
    const float* src = (row < NBOT) ? &Wq[(size_t)row * ND] : &Wk[(size_t)(row - NBOT) * ND];
    for (int c = threadIdx.x; c < ND; c += blockDim.x)
        W[(size_t)row * ND + c] = __float2half_rn(src[c]);
    if (threadIdx.x == 0)
        bias[row] = (row < NBOT) ? bq[row] : bk[row - NBOT];
}

// ---- prep: X fp32 -> fp16 copy + fp16 transpose ----
__global__ void transpose_half(const float* __restrict__ X,
                               __half* __restrict__ Xh, __half* __restrict__ Xt) {
    __shared__ float tile[32][33];
    const int b = blockIdx.z;
    const int d0 = blockIdx.x * 32, t0 = blockIdx.y * 32;
    const float* Xb = X  + (long long)b * NT * ND;
    __half* Xhb     = Xh + (long long)b * NT * ND;
    __half* Xtb     = Xt + (long long)b * ND * NT;
    const int tx = threadIdx.x, ty = threadIdx.y;
#pragma unroll
    for (int i = 0; i < 4; ++i) {
        const int t = t0 + ty + i * 8;
        const float v = Xb[(long long)t * ND + d0 + tx];
        Xhb[(long long)t * ND + d0 + tx] = __float2half_rn(v);
        tile[ty + i * 8][tx] = v;
    }
    __syncthreads();
#pragma unroll
    for (int i = 0; i < 4; ++i) {
        const int d = d0 + ty + i * 8;
        Xtb[(long long)d * NT + t0 + tx] = __float2half_rn(tile[tx][ty + i * 8]);
    }
}

// ---- softmax + combine: reads ONLY the allowed prefix (j <= i-4) of S ----
// Masked cols: exp contribution is exactly 0 (matches fp32 reference underflow),
// so C = 0.7*decay there. Rows i<4: fully masked -> uniform softmax 1/NT.
__global__ void __launch_bounds__(256)
softmax_combine(const float* __restrict__ decay, const float* __restrict__ S,
                __half* __restrict__ C)
{
    __shared__ float red[8];
    const int i = blockIdx.x;
    const long long base = ((long long)blockIdx.y * NT + i) * NT;
    const int tid = threadIdx.x;
    const int lane = tid & 31, wid = tid >> 5;
    const int nallow = i - 3;

    if (nallow <= 0) {           // fully masked row: uniform softmax
        const float add = 0.3f / (float)NT;
#pragma unroll
        for (int p = 0; p < 16; ++p) {
            const long long idx = base + tid + 256 * p;
            C[idx] = __float2half_rn(fmaf(0.7f, decay[idx], add));
        }
        return;
    }

    const float NEG = __int_as_float(0xff800000);  // -inf
    float v[16];
#pragma unroll
    for (int p = 0; p < 16; ++p) {
        const int c = tid + 256 * p;
        v[p] = (c < nallow) ? S[base + c] : NEG;
    }

    float mx = v[0];
#pragma unroll
    for (int p = 1; p < 16; ++p) mx = fmaxf(mx, v[p]);
#pragma unroll
    for (int o = 16; o > 0; o >>= 1) mx = fmaxf(mx, __shfl_xor_sync(0xffffffffu, mx, o));
    if (lane == 0) red[wid] = mx;
    __syncthreads();
    float bm = red[0];
#pragma unroll
    for (int i2 = 1; i2 < 8; ++i2) bm = fmaxf(bm, red[i2]);

    float s = 0.f;
#pragma unroll
    for (int p = 0; p < 16; ++p) { v[p] = __expf(v[p] - bm); s += v[p]; }  // masked -> 0
#pragma unroll
    for (int o = 16; o > 0; o >>= 1) s += __shfl_xor_sync(0xffffffffu, s, o);
    __syncthreads();
    if (lane == 0) red[wid] = s;
    __syncthreads();
    float ts = 0.f;
#pragma unroll
    for (int i2 = 0; i2 < 8; ++i2) ts += red[i2];

    const float inv = 0.3f / ts;
#pragma unroll
    for (int p = 0; p < 16; ++p) {
        const long long idx = base + tid + 256 * p;
        C[idx] = __float2half_rn(fmaf(v[p], inv, 0.7f * decay[idx]));  // masked: v=0 -> 0.7d
    }
}

extern "C" void kernel_launch(void* const* d_in, const int* in_sizes, int n_in,
                              void* d_out, int out_size)
{
    (void)in_sizes; (void)n_in; (void)out_size;
    const float* X     = (const float*)d_in[0];
    const float* decay = (const float*)d_in[1];
    const float* Wq    = (const float*)d_in[2];
    const float* bq    = (const float*)d_in[3];
    const float* Wk    = (const float*)d_in[4];
    const float* bk    = (const float*)d_in[5];
    float*       out   = (float*)d_out;

    float  *Sp, *biasp;
    __half *Cp, *Xhp, *Xtp, *qkp, *Wp;
    cudaGetSymbolAddress((void**)&Sp,   g_S);
    cudaGetSymbolAddress((void**)&Cp,   g_C);
    cudaGetSymbolAddress((void**)&Xhp,  g_Xh);
    cudaGetSymbolAddress((void**)&Xtp,  g_Xth);
    cudaGetSymbolAddress((void**)&qkp,  g_qk);
    cudaGetSymbolAddress((void**)&Wp,   g_W);
    cudaGetSymbolAddress((void**)&biasp, g_bias);

    cudaFuncSetAttribute(gemm_h<0>, cudaFuncAttributeMaxDynamicSharedMemorySize, SMEM_BYTES);
    cudaFuncSetAttribute(gemm_h<1>, cudaFuncAttributeMaxDynamicSharedMemorySize, SMEM_BYTES);
    cudaFuncSetAttribute(gemm_h<2>, cudaFuncAttributeMaxDynamicSharedMemorySize, SMEM_BYTES);

    // prep
    prep_w<<<NQK, 256>>>(Wq, Wk, bq, bk, Wp, biasp);
    transpose_half<<<dim3(ND / 32, NT / 32, NB), dim3(32, 8)>>>(X, Xhp, Xtp);

    // qk = X @ [Wq;Wk]^T + bias   (M = B*T = 16384, N = 512, K = 2048) -> fp16
    gemm_h<1><<<dim3(NQK / BN, (NB * NT) / BM, 1), NTH, SMEM_BYTES>>>(
        Xhp, ND, 0LL, Wp, ND, 0LL, qkp, NQK, 0LL, ND, biasp, 1.f);

    // S = scale * q @ k^T (lower-triangular tiles only)  (per batch, M = N = T, K = 256)
    gemm_h<2><<<dim3(NT / BN, NT / BM, NB), NTH, SMEM_BYTES>>>(
        qkp,        NQK, (long long)NT * NQK,
        qkp + NBOT, NQK, (long long)NT * NQK,
        Sp,         NT,  (long long)NT * NT,
        NBOT, nullptr, 0.0625f);

    // combined = 0.7*decay + 0.3*softmax(S)  -> fp16
    softmax_combine<<<dim3(NT, NB), 256>>>(decay, Sp, Cp);

    // out = combined @ X = combined @ Xt^T  (per batch, M = T, N = D, K = T) -> fp32
    gemm_h<0><<<dim3(ND / BN, NT / BM, NB), NTH, SMEM_BYTES>>>(
        Cp,  NT, (long long)NT * NT,
        Xtp, NT, (long long)ND * NT,
        out, ND, (long long)NT * ND,
        NT, nullptr, 1.f);
}